// round 14
// baseline (speedup 1.0000x reference)
#include <cuda_runtime.h>
#include <cuda_bf16.h>
#include <math.h>
#include <stdint.h>

#define NTOK   16384
#define DMODEL 1024
#define NEXP   64
#define F1     256

typedef __nv_bfloat16 bf16;

// ================= device scratch =================
__device__ float g_kv  [NEXP * 2 * DMODEL];
__device__ float g_c   [DMODEL];
__device__ float g_W2gT[F1 * DMODEL];
__device__ float g_c2  [F1];
__device__ float g_part [16 * NEXP * 2 * DMODEL];  // kv partials (z=16)
__device__ float g_part2[8 * F1 * DMODEL];         // W2gT partials (z=8)
__device__ bf16  g_MTb [DMODEL * DMODEL];
__device__ bf16  g_MTs [DMODEL * DMODEL];
__device__ bf16  g_Gtb [F1 * DMODEL];
__device__ bf16  g_Gts [F1 * DMODEL];
__device__ bf16  g_xb  [NTOK * DMODEL];
__device__ bf16  g_xs  [NTOK * DMODEL];
__device__ bf16  g_ab  [NTOK * DMODEL];
__device__ bf16  g_as  [NTOK * DMODEL];
__device__ float g_h1  [NTOK * F1];
__device__ float g_zero[DMODEL];

// ================= helpers =================
__device__ __forceinline__ uint32_t smem_u32(const void* p) {
    uint32_t a;
    asm("{ .reg .u64 t; cvta.to.shared.u64 t, %1; cvt.u32.u64 %0, t; }" : "=r"(a) : "l"(p));
    return a;
}
__device__ __forceinline__ void cp16(uint32_t dst, const void* src) {
    asm volatile("cp.async.cg.shared.global [%0], [%1], 16;" :: "r"(dst), "l"(src));
}
#define CP_COMMIT() asm volatile("cp.async.commit_group;" ::: "memory")
#define CP_WAIT1()  asm volatile("cp.async.wait_group 1;" ::: "memory")
#define CP_WAIT0()  asm volatile("cp.async.wait_group 0;" ::: "memory")

#define LDSM4(r0, r1, r2, r3, a)                                               \
    asm volatile("ldmatrix.sync.aligned.m8n8.x4.shared.b16 {%0,%1,%2,%3}, [%4];" \
                 : "=r"(r0), "=r"(r1), "=r"(r2), "=r"(r3) : "r"(a))

__device__ __forceinline__ void mma_bf16(float& d0, float& d1, float& d2, float& d3,
                                         uint32_t a0, uint32_t a1, uint32_t a2, uint32_t a3,
                                         uint32_t b0, uint32_t b1) {
    asm volatile(
        "mma.sync.aligned.m16n8k16.row.col.f32.bf16.bf16.f32 "
        "{%0,%1,%2,%3}, {%4,%5,%6,%7}, {%8,%9}, {%0,%1,%2,%3};"
        : "+f"(d0), "+f"(d1), "+f"(d2), "+f"(d3)
        : "r"(a0), "r"(a1), "r"(a2), "r"(a3), "r"(b0), "r"(b1));
}
__device__ __forceinline__ uint32_t pack_bf16(float lo, float hi) {
    uint16_t l = __bfloat16_as_ushort(__float2bfloat16_rn(lo));
    uint16_t h = __bfloat16_as_ushort(__float2bfloat16_rn(hi));
    return (uint32_t)l | ((uint32_t)h << 16);
}

// ================= fp32 -> bf16 split of x =================
__global__ void split_x(const float4* __restrict__ x, uint2* __restrict__ xb,
                        uint2* __restrict__ xs) {
    long i = (long)blockIdx.x * 256 + threadIdx.x;
    float4 v = x[i];
    float bx = __bfloat162float(__float2bfloat16_rn(v.x));
    float by = __bfloat162float(__float2bfloat16_rn(v.y));
    float bz = __bfloat162float(__float2bfloat16_rn(v.z));
    float bw = __bfloat162float(__float2bfloat16_rn(v.w));
    uint2 b, s;
    b.x = pack_bf16(bx, by); b.y = pack_bf16(bz, bw);
    s.x = pack_bf16(v.x - bx, v.y - by);
    s.y = pack_bf16(v.z - bz, v.w - bw);
    xb[i] = b; xs[i] = s;
}

// ================= split-K SIMT SGEMM, B = [k][n] row-major (z slices of 128) =====
__global__ __launch_bounds__(256)
void sgemm_splitk(const float* __restrict__ A, const float* __restrict__ B,
                  float* __restrict__ P, int Arows, int N) {
    __shared__ float As[8][68];
    __shared__ float Bs[8][128];
    const int t = threadIdx.x;
    const int rowBase = blockIdx.y * 64;
    const int colBase = blockIdx.x * 128;
    const int k0 = blockIdx.z * 128;
    const int m0 = (t >> 4) * 4;
    const int n0 = (t & 15) * 8;
    const int am = t >> 2, akq = (t & 3) * 2;
    const int bn = t & 127, bkb = t >> 7;

    float acc[4][8];
#pragma unroll
    for (int i = 0; i < 4; i++)
#pragma unroll
        for (int j = 0; j < 8; j++) acc[i][j] = 0.f;

    for (int kc = 0; kc < 16; kc++) {
        int kk = k0 + kc * 8;
        float2 av = *(const float2*)(A + (long)(rowBase + am) * 1024 + kk + akq);
        As[akq][am] = av.x; As[akq + 1][am] = av.y;
#pragma unroll
        for (int j = 0; j < 4; j++)
            Bs[bkb + 2 * j][bn] = B[(long)(kk + bkb + 2 * j) * N + colBase + bn];
        __syncthreads();
#pragma unroll
        for (int k = 0; k < 8; k++) {
            float a[4], b[8];
            *(float4*)&a[0] = *(const float4*)&As[k][m0];
            *(float4*)&b[0] = *(const float4*)&Bs[k][n0];
            *(float4*)&b[4] = *(const float4*)&Bs[k][n0 + 4];
#pragma unroll
            for (int i = 0; i < 4; i++)
#pragma unroll
                for (int j = 0; j < 8; j++)
                    acc[i][j] = fmaf(a[i], b[j], acc[i][j]);
        }
        __syncthreads();
    }

    float* Pz = P + (long)blockIdx.z * Arows * N;
#pragma unroll
    for (int i = 0; i < 4; i++) {
        float* op = Pz + (long)(rowBase + m0 + i) * N + colBase + n0;
        *(float4*)op       = make_float4(acc[i][0], acc[i][1], acc[i][2], acc[i][3]);
        *(float4*)(op + 4) = make_float4(acc[i][4], acc[i][5], acc[i][6], acc[i][7]);
    }
}

// ================= split-K SIMT SGEMM, B = [n][k] (A@B^T), z slices of 64 =========
__global__ __launch_bounds__(256)
void sgemm_splitk_bt(const float* __restrict__ A, const float* __restrict__ B,
                     float* __restrict__ P, int Arows, int N) {
    __shared__ float As[8][68];
    __shared__ float Bs[8][132];
    const int t = threadIdx.x;
    const int rowBase = blockIdx.y * 64;
    const int colBase = blockIdx.x * 128;
    const int k0 = blockIdx.z * 64;
    const int m0 = (t >> 4) * 4;
    const int n0 = (t & 15) * 8;
    const int am = t >> 2, akq = (t & 3) * 2;
    const int bn = t >> 1, bkq = (t & 1) * 4;

    float acc[4][8];
#pragma unroll
    for (int i = 0; i < 4; i++)
#pragma unroll
        for (int j = 0; j < 8; j++) acc[i][j] = 0.f;

    for (int kc = 0; kc < 8; kc++) {
        int kk = k0 + kc * 8;
        float2 av = *(const float2*)(A + (long)(rowBase + am) * 1024 + kk + akq);
        As[akq][am] = av.x; As[akq + 1][am] = av.y;
        float4 bv = *(const float4*)(B + (long)(colBase + bn) * 1024 + kk + bkq);
        Bs[bkq + 0][bn] = bv.x; Bs[bkq + 1][bn] = bv.y;
        Bs[bkq + 2][bn] = bv.z; Bs[bkq + 3][bn] = bv.w;
        __syncthreads();
#pragma unroll
        for (int k = 0; k < 8; k++) {
            float a[4], b[8];
            *(float4*)&a[0] = *(const float4*)&As[k][m0];
            *(float4*)&b[0] = *(const float4*)&Bs[k][n0];
            *(float4*)&b[4] = *(const float4*)&Bs[k][n0 + 4];
#pragma unroll
            for (int i = 0; i < 4; i++)
#pragma unroll
                for (int j = 0; j < 8; j++)
                    acc[i][j] = fmaf(a[i], b[j], acc[i][j]);
        }
        __syncthreads();
    }

    float* Pz = P + (long)blockIdx.z * Arows * N;
#pragma unroll
    for (int i = 0; i < 4; i++) {
        float* op = Pz + (long)(rowBase + m0 + i) * N + colBase + n0;
        *(float4*)op       = make_float4(acc[i][0], acc[i][1], acc[i][2], acc[i][3]);
        *(float4*)(op + 4) = make_float4(acc[i][4], acc[i][5], acc[i][6], acc[i][7]);
    }
}

// ================= split-K reduce + bias (nz partials) =================
__global__ void reduce_splitk(const float* __restrict__ P, const float* __restrict__ bias,
                              float* __restrict__ C, int total, int N, int nz) {
    int i = blockIdx.x * 256 + threadIdx.x;
    if (i < total) {
        float s = 0.f;
        for (int z = 0; z < nz; z++) s += P[(long)z * total + i];
        C[i] = s + bias[i % N];
    }
}

// ================= build M^T (bf16 split) + c, tiled, fused k-reduce =================
#define BM_SMEM ((8192 + 4096 + 64) * 4)
__global__ __launch_bounds__(256)
void build_M_c(const float* __restrict__ ipw, const float* __restrict__ ipb,
               const float* __restrict__ part,
               bf16* __restrict__ MTb, bf16* __restrict__ MTs, float* __restrict__ c) {
    extern __shared__ float bm[];
    float* wqs = bm;             // [64][128]
    float* ksm = bm + 8192;      // [64][64]  (e, hd)
    float* bqs = ksm + 4096;     // [64]
    const int h = blockIdx.y;
    const int d0 = blockIdx.x * 128;
    const int t = threadIdx.x;

    for (int idx = t; idx < 8192; idx += 256) {
        int hd = idx >> 7, dd = idx & 127;
        wqs[idx] = ipw[(long)(h * 64 + hd) * 1024 + d0 + dd];
    }
    for (int idx = t; idx < 4096; idx += 256) {
        int e = idx >> 6, hd = idx & 63;
        float s = 0.f;
#pragma unroll
        for (int z = 0; z < 16; z++)
            s += part[(long)z * 131072 + e * 2048 + h * 64 + hd];
        ksm[idx] = s + ipb[1024 + h * 64 + hd];
    }
    if (t < 64) bqs[t] = ipb[h * 64 + t];
    __syncthreads();

    const int dd = t & 127;
    const int e0 = (t >> 7) * 32;
#pragma unroll
    for (int eb = 0; eb < 4; eb++) {
        float acc[8];
#pragma unroll
        for (int i = 0; i < 8; i++) acc[i] = 0.f;
#pragma unroll 8
        for (int hd = 0; hd < 64; hd++) {
            float wv = wqs[hd * 128 + dd];
#pragma unroll
            for (int e8 = 0; e8 < 8; e8++)
                acc[e8] = fmaf(wv, ksm[(e0 + eb * 8 + e8) * 64 + hd], acc[e8]);
        }
#pragma unroll
        for (int e8 = 0; e8 < 8; e8++) {
            int he = h * 64 + e0 + eb * 8 + e8;
            bf16 b = __float2bfloat16_rn(acc[e8]);
            MTb[(long)he * 1024 + d0 + dd] = b;
            MTs[(long)he * 1024 + d0 + dd] =
                __float2bfloat16_rn(acc[e8] - __bfloat162float(b));
        }
    }
    if (blockIdx.x == 0 && t < 64) {
        float s = 0.f;
        for (int hd = 0; hd < 64; hd++) s = fmaf(ksm[t * 64 + hd], bqs[hd], s);
        c[h * 64 + t] = s;
    }
}

// ================= build Gt (bf16 split) + c2 =================
__global__ void build_Gt(const float* __restrict__ W2gT, const float* __restrict__ kv,
                         const float* __restrict__ gw1, const float* __restrict__ opb,
                         const float* __restrict__ gb1,
                         bf16* __restrict__ Gtb, bf16* __restrict__ Gts,
                         float* __restrict__ c2) {
    int j = blockIdx.x;
    __shared__ float wrow[1024];
    int t = threadIdx.x;
    for (int i = t; i < 1024; i += 256) wrow[i] = W2gT[(long)j * 1024 + i];
    __syncthreads();
    for (int he = t; he < 1024; he += 256) {
        int h = he >> 6, e = he & 63;
        const float* v = kv + (long)e * 2048 + 1024 + h * 64;
        float s = 0.f;
#pragma unroll 8
        for (int hd = 0; hd < 64; hd++)
            s = fmaf(v[hd], wrow[h * 64 + hd], s);
        bf16 b = __float2bfloat16_rn(s);
        Gtb[(long)j * 1024 + he] = b;
        Gts[(long)j * 1024 + he] = __float2bfloat16_rn(s - __bfloat162float(b));
    }
    if (t < 32) {
        float s = 0.f;
        const float* g = gw1 + (long)j * 1024;
        for (int d = t; d < 1024; d += 32) s = fmaf(opb[d], g[d], s);
#pragma unroll
        for (int off = 16; off > 0; off >>= 1)
            s += __shfl_xor_sync(0xffffffffu, s, off);
        if (t == 0) c2[j] = s + gb1[j];
    }
}

// ================= bf16 3-split tensor-core GEMM (ldmatrix + mma.sync) =================
#define ROWW 20
#define TILE_B 10240
#define STAGE_B (4 * TILE_B)
#define SMEM_BYTES (2 * STAGE_B)

template<int MODE>
__global__ __launch_bounds__(256, 2)
void tgemm(const bf16* __restrict__ Ab, const bf16* __restrict__ As,
           const bf16* __restrict__ Bb, const bf16* __restrict__ Bs,
           const float* __restrict__ bias,
           uint32_t* __restrict__ outB, uint32_t* __restrict__ outS,
           float* __restrict__ outF, int Ncols) {
    extern __shared__ uint32_t sm32[];
    uint32_t smu = smem_u32(sm32);

    const int t = threadIdx.x;
    const int w = t >> 5, lane = t & 31;
    const int wm = w >> 1, wn = w & 1;
    const int q = lane >> 2, c4 = lane & 3;

    const int rowBase = blockIdx.y * 128;
    const int colBase = blockIdx.x * 128;

    const int lr = t >> 1;
    const int ls = t & 1;
    const bf16* gAb = Ab + (long)(rowBase + lr) * 1024;
    const bf16* gAs = As + (long)(rowBase + lr) * 1024;
    const bf16* gBb = Bb + (long)(colBase + lr) * 1024;
    const bf16* gBs = Bs + (long)(colBase + lr) * 1024;
    const uint32_t dRow = smu + lr * (ROWW * 4);

    const int lm8 = lane & 7;
    const uint32_t aOff = (uint32_t)(wm * 32 + lm8 + ((lane >> 3) & 1) * 8) * 80
                          + ((lane >> 4) & 1) * 16;
    const uint32_t bOff = (uint32_t)(wn * 64 + lm8 + ((lane >> 4) & 1) * 8) * 80
                          + ((lane >> 3) & 1) * 16;

    float acc[2][8][4];
#pragma unroll
    for (int mt = 0; mt < 2; mt++)
#pragma unroll
        for (int nt = 0; nt < 8; nt++)
#pragma unroll
            for (int i = 0; i < 4; i++) acc[mt][nt][i] = 0.f;

#define LOAD_STAGE(st, ck) do {                                                  \
    int kofs = (ck) * 32;                                                        \
    uint32_t sb = (st) * STAGE_B;                                                \
    _Pragma("unroll")                                                            \
    for (int j = 0; j < 2; j++) {                                                \
        int seg = ls * 2 + j;                                                    \
        cp16(dRow + sb + 0 * TILE_B + seg * 16, gAb + kofs + seg * 8);           \
        cp16(dRow + sb + 1 * TILE_B + seg * 16, gAs + kofs + seg * 8);           \
        cp16(dRow + sb + 2 * TILE_B + seg * 16, gBb + kofs + seg * 8);           \
        cp16(dRow + sb + 3 * TILE_B + seg * 16, gBs + kofs + seg * 8);           \
    }                                                                            \
} while (0)

    LOAD_STAGE(0, 0);
    CP_COMMIT();

    const int NC = 1024 / 32;
    for (int ck = 0; ck < NC; ck++) {
        int buf = ck & 1;
        if (ck + 1 < NC) {
            LOAD_STAGE(buf ^ 1, ck + 1);
            CP_COMMIT();
            CP_WAIT1();
        } else {
            CP_WAIT0();
        }
        __syncthreads();

        const uint32_t s0 = smu + buf * STAGE_B;
        const uint32_t aAb = s0 + aOff;
        const uint32_t aAs = s0 + TILE_B + aOff;
        const uint32_t bBb = s0 + 2 * TILE_B + bOff;
        const uint32_t bBs = s0 + 3 * TILE_B + bOff;

#pragma unroll
        for (int ks = 0; ks < 2; ks++) {
            uint32_t fab[2][4], fas[2][4];
            LDSM4(fab[0][0], fab[0][1], fab[0][2], fab[0][3], aAb + ks * 32);
            LDSM4(fab[1][0], fab[1][1], fab[1][2], fab[1][3], aAb + 1280 + ks * 32);
            LDSM4(fas[0][0], fas[0][1], fas[0][2], fas[0][3], aAs + ks * 32);
            LDSM4(fas[1][0], fas[1][1], fas[1][2], fas[1][3], aAs + 1280 + ks * 32);
#pragma unroll
            for (int jh = 0; jh < 2; jh++) {
                uint32_t fbb[4][2], fbs[4][2];
                LDSM4(fbb[0][0], fbb[0][1], fbb[1][0], fbb[1][1],
                      bBb + (2 * jh) * 1280 + ks * 32);
                LDSM4(fbb[2][0], fbb[2][1], fbb[3][0], fbb[3][1],
                      bBb + (2 * jh + 1) * 1280 + ks * 32);
                LDSM4(fbs[0][0], fbs[0][1], fbs[1][0], fbs[1][1],
                      bBs + (2 * jh) * 1280 + ks * 32);
                LDSM4(fbs[2][0], fbs[2][1], fbs[3][0], fbs[3][1],
                      bBs + (2 * jh + 1) * 1280 + ks * 32);
#pragma unroll
                for (int l = 0; l < 4; l++)
#pragma unroll
                    for (int mt = 0; mt < 2; mt++) {
                        float* d = acc[mt][4 * jh + l];
                        mma_bf16(d[0], d[1], d[2], d[3],
                                 fab[mt][0], fab[mt][1], fab[mt][2], fab[mt][3],
                                 fbb[l][0], fbb[l][1]);
                    }
#pragma unroll
                for (int l = 0; l < 4; l++)
#pragma unroll
                    for (int mt = 0; mt < 2; mt++) {
                        float* d = acc[mt][4 * jh + l];
                        mma_bf16(d[0], d[1], d[2], d[3],
                                 fab[mt][0], fab[mt][1], fab[mt][2], fab[mt][3],
                                 fbs[l][0], fbs[l][1]);
                    }
#pragma unroll
                for (int l = 0; l < 4; l++)
#pragma unroll
                    for (int mt = 0; mt < 2; mt++) {
                        float* d = acc[mt][4 * jh + l];
                        mma_bf16(d[0], d[1], d[2], d[3],
                                 fas[mt][0], fas[mt][1], fas[mt][2], fas[mt][3],
                                 fbb[l][0], fbb[l][1]);
                    }
            }
        }
        __syncthreads();
    }

    const int colB = colBase + wn * 64;
    float bv[16];
#pragma unroll
    for (int nt = 0; nt < 8; nt++) {
#pragma unroll
        for (int j = 0; j < 2; j++)
            bv[nt * 2 + j] = bias[colB + nt * 8 + 2 * c4 + j];
    }

#pragma unroll
    for (int mt = 0; mt < 2; mt++) {
#pragma unroll
        for (int h = 0; h < 2; h++) {
            int row = rowBase + wm * 32 + mt * 16 + q + h * 8;
            float v[16];
#pragma unroll
            for (int nt = 0; nt < 8; nt++) {
                v[nt * 2 + 0] = acc[mt][nt][2 * h + 0] + bv[nt * 2 + 0];
                v[nt * 2 + 1] = acc[mt][nt][2 * h + 1] + bv[nt * 2 + 1];
            }
            if (MODE == 1) {
#pragma unroll
                for (int i = 0; i < 16; i++) v[i] *= 0.125f;
                float m = v[0];
#pragma unroll
                for (int i = 1; i < 16; i++) m = fmaxf(m, v[i]);
                m = fmaxf(m, __shfl_xor_sync(0xffffffffu, m, 1));
                m = fmaxf(m, __shfl_xor_sync(0xffffffffu, m, 2));
                float s = 0.f;
#pragma unroll
                for (int i = 0; i < 16; i++) { v[i] = __expf(v[i] - m); s += v[i]; }
                s += __shfl_xor_sync(0xffffffffu, s, 1);
                s += __shfl_xor_sync(0xffffffffu, s, 2);
                float inv = 1.f / s;
#pragma unroll
                for (int i = 0; i < 16; i++) v[i] *= inv;
                uint32_t* ob = outB + (long)row * (Ncols / 2) + (colB >> 1) + c4;
                uint32_t* os = outS + (long)row * (Ncols / 2) + (colB >> 1) + c4;
#pragma unroll
                for (int nt = 0; nt < 8; nt++) {
                    float v0 = v[nt * 2], v1 = v[nt * 2 + 1];
                    float b0 = __bfloat162float(__float2bfloat16_rn(v0));
                    float b1 = __bfloat162float(__float2bfloat16_rn(v1));
                    ob[nt * 4] = pack_bf16(b0, b1);
                    os[nt * 4] = pack_bf16(v0 - b0, v1 - b1);
                }
            }
            if (MODE == 2) {
#pragma unroll
                for (int i = 0; i < 16; i++)
                    v[i] = 0.5f * v[i] * (1.0f + erff(v[i] * 0.70710678118654752f));
                float* op = outF + (long)row * Ncols + colB + 2 * c4;
#pragma unroll
                for (int nt = 0; nt < 8; nt++) {
                    op[nt * 8 + 0] = v[nt * 2 + 0];
                    op[nt * 8 + 1] = v[nt * 2 + 1];
                }
            }
        }
    }
#undef LOAD_STAGE
}

// ================= gating: smem-cached w2, 32 tokens/block =================
#define GATE_SMEM (64 * 257 * 4 + 4 * 256 * 4 + 4 * 64 * 4)

__global__ __launch_bounds__(256)
void gating_kernel(const float* __restrict__ h1, const float* __restrict__ w2,
                   const float* __restrict__ b2, float* __restrict__ out) {
    extern __shared__ float gs[];
    float* w2s  = gs;
    float* hrow = gs + 64 * 257;
    float* lg   = hrow + 4 * 256;
    int t = threadIdx.x;
    int grp = t >> 6, e = t & 63;
    for (int i = t; i < 64 * 256; i += 256)
        w2s[(i >> 8) * 257 + (i & 255)] = w2[i];
    __syncthreads();

    for (int rep = 0; rep < 8; rep++) {
        int token = blockIdx.x * 32 + rep * 4 + grp;
        for (int j = e; j < 256; j += 64) hrow[grp * 256 + j] = h1[(long)token * 256 + j];
        __syncthreads();
        float acc = 0.f;
        const float* wr = w2s + e * 257;
        const float* hr = hrow + grp * 256;
#pragma unroll 8
        for (int j = 0; j < 256; j++) acc = fmaf(hr[j], wr[j], acc);
        lg[grp * 64 + e] = acc + b2[e];
        __syncthreads();
        if (e == 0) {
            const float* L = lg + grp * 64;
            int i1 = 0; float v1 = L[0];
            for (int k = 1; k < NEXP; k++) if (L[k] > v1) { v1 = L[k]; i1 = k; }
            int i2 = -1; float v2 = -1e30f;
            for (int k = 0; k < NEXP; k++) if (k != i1 && L[k] > v2) { v2 = L[k]; i2 = k; }
            float s = 0.f;
            for (int k = 0; k < NEXP; k++) s += __expf(L[k] - v1);
            float p1 = 1.0f / s;
            float p2 = __expf(v2 - v1) / s;
            float wsum = p1 + p2 + 1e-8f;
            out[token * 2 + 0] = (float)i1;
            out[token * 2 + 1] = (float)i2;
            out[NTOK * 2 + token * 2 + 0] = p1 / wsum;
            out[NTOK * 2 + token * 2 + 1] = p2 / wsum;
        }
        __syncthreads();
    }
}

// ================= launch =================
extern "C" void kernel_launch(void* const* d_in, const int* in_sizes, int n_in,
                              void* d_out, int out_size) {
    const float* x   = (const float*)d_in[0];
    const float* emb = (const float*)d_in[1];
    const float* ipw = (const float*)d_in[2];
    const float* ipb = (const float*)d_in[3];
    const float* opw = (const float*)d_in[4];
    const float* opb = (const float*)d_in[5];
    const float* gw1 = (const float*)d_in[6];
    const float* gb1 = (const float*)d_in[7];
    const float* gw2 = (const float*)d_in[8];
    const float* gb2 = (const float*)d_in[9];
    float* out = (float*)d_out;

    float *kv, *c, *W2gT, *c2, *part, *part2, *h1, *zero;
    bf16 *MTb, *MTs, *Gtb, *Gts, *xb, *xs, *ab, *as_;
    cudaGetSymbolAddress((void**)&kv,    g_kv);
    cudaGetSymbolAddress((void**)&c,     g_c);
    cudaGetSymbolAddress((void**)&W2gT,  g_W2gT);
    cudaGetSymbolAddress((void**)&c2,    g_c2);
    cudaGetSymbolAddress((void**)&part,  g_part);
    cudaGetSymbolAddress((void**)&part2, g_part2);
    cudaGetSymbolAddress((void**)&h1,    g_h1);
    cudaGetSymbolAddress((void**)&zero,  g_zero);
    cudaGetSymbolAddress((void**)&MTb,   g_MTb);
    cudaGetSymbolAddress((void**)&MTs,   g_MTs);
    cudaGetSymbolAddress((void**)&Gtb,   g_Gtb);
    cudaGetSymbolAddress((void**)&Gts,   g_Gts);
    cudaGetSymbolAddress((void**)&xb,    g_xb);
    cudaGetSymbolAddress((void**)&xs,    g_xs);
    cudaGetSymbolAddress((void**)&ab,    g_ab);
    cudaGetSymbolAddress((void**)&as_,   g_as);

    static cudaStream_t s1 = nullptr, s2 = nullptr;
    static cudaEvent_t evRoot = nullptr, evSplit = nullptr, evKv = nullptr, evGt = nullptr;
    if (s1 == nullptr) {
        cudaStreamCreateWithFlags(&s1, cudaStreamNonBlocking);
        cudaStreamCreateWithFlags(&s2, cudaStreamNonBlocking);
        cudaEventCreateWithFlags(&evRoot,  cudaEventDisableTiming);
        cudaEventCreateWithFlags(&evSplit, cudaEventDisableTiming);
        cudaEventCreateWithFlags(&evKv,    cudaEventDisableTiming);
        cudaEventCreateWithFlags(&evGt,    cudaEventDisableTiming);
        cudaFuncSetAttribute(tgemm<1>, cudaFuncAttributeMaxDynamicSharedMemorySize, SMEM_BYTES);
        cudaFuncSetAttribute(tgemm<2>, cudaFuncAttributeMaxDynamicSharedMemorySize, SMEM_BYTES);
        cudaFuncSetAttribute(gating_kernel, cudaFuncAttributeMaxDynamicSharedMemorySize, GATE_SMEM);
        cudaFuncSetAttribute(build_M_c, cudaFuncAttributeMaxDynamicSharedMemorySize, BM_SMEM);
    }

    // fork
    cudaEventRecord(evRoot, 0);
    cudaStreamWaitEvent(s1, evRoot, 0);
    cudaStreamWaitEvent(s2, evRoot, 0);

    // s1: split x (input to GEMM1)
    split_x<<<NTOK * DMODEL / 4 / 256, 256, 0, s1>>>((const float4*)x, (uint2*)xb, (uint2*)xs);
    cudaEventRecord(evSplit, s1);

    // s2: W2gT chain (independent of kv until build_Gt)
    sgemm_splitk<<<dim3(8, 4, 8), 256, 0, s2>>>(gw1, opw, part2, 256, 1024);
    reduce_splitk<<<(256 * 1024 + 255) / 256, 256, 0, s2>>>(part2, zero, W2gT, 256 * 1024, 1024, 8);

    // s0: kv partials (critical path), split-K=16
    sgemm_splitk_bt<<<dim3(16, 1, 16), 256>>>(emb, ipw + 1024 * 1024, part, 64, 2048);
    cudaEventRecord(evKv, 0);

    // s2: kv reduce (for v half) + build_Gt, hidden under build_M_c/GEMM1
    cudaStreamWaitEvent(s2, evKv, 0);
    reduce_splitk<<<(64 * 2048 + 255) / 256, 256, 0, s2>>>(part, ipb + 1024, kv, 64 * 2048, 2048, 16);
    build_Gt<<<256, 256, 0, s2>>>(W2gT, kv, gw1, opb, gb1, Gtb, Gts, c2);
    cudaEventRecord(evGt, s2);

    // s0: M builder (fused k-reduce from partials) then GEMM1 (single launch)
    build_M_c<<<dim3(8, 16), 256, BM_SMEM>>>(ipw, ipb, part, MTb, MTs, c);
    cudaStreamWaitEvent(0, evSplit, 0);
    tgemm<1><<<dim3(8, 128), 256, SMEM_BYTES>>>(xb, xs, MTb, MTs, c,
                                                (uint32_t*)ab, (uint32_t*)as_, nullptr, 1024);
    cudaStreamWaitEvent(0, evGt, 0);
    tgemm<2><<<dim3(2, 128), 256, SMEM_BYTES>>>(ab, as_, Gtb, Gts, c2,
                                                nullptr, nullptr, h1, 256);
    gating_kernel<<<NTOK / 32, 256, GATE_SMEM>>>(h1, gw2, gb2, out);
    (void)in_sizes; (void)n_in; (void)out_size;
}

// round 16
// speedup vs baseline: 1.0467x; 1.0467x over previous
#include <cuda_runtime.h>
#include <cuda_bf16.h>
#include <math.h>
#include <stdint.h>

#define NTOK   16384
#define DMODEL 1024
#define NEXP   64
#define F1     256

typedef __nv_bfloat16 bf16;

// ================= device scratch =================
__device__ float g_kv  [NEXP * 2 * DMODEL];
__device__ float g_c   [DMODEL];
__device__ float g_W2gT[F1 * DMODEL];
__device__ float g_c2  [F1];
__device__ float g_part [16 * NEXP * 2 * DMODEL];  // kv partials (z=16)
__device__ float g_part2[8 * F1 * DMODEL];         // W2gT partials (z=8)
__device__ int   g_flags[128];                     // per-row-block attn ready count
__device__ bf16  g_MTb [DMODEL * DMODEL];
__device__ bf16  g_MTs [DMODEL * DMODEL];
__device__ bf16  g_Gtb [F1 * DMODEL];
__device__ bf16  g_Gts [F1 * DMODEL];
__device__ bf16  g_xb  [NTOK * DMODEL];
__device__ bf16  g_xs  [NTOK * DMODEL];
__device__ bf16  g_ab  [NTOK * DMODEL];
__device__ bf16  g_as  [NTOK * DMODEL];
__device__ float g_h1  [NTOK * F1];
__device__ float g_zero[DMODEL];

// ================= helpers =================
__device__ __forceinline__ uint32_t smem_u32(const void* p) {
    uint32_t a;
    asm("{ .reg .u64 t; cvta.to.shared.u64 t, %1; cvt.u32.u64 %0, t; }" : "=r"(a) : "l"(p));
    return a;
}
__device__ __forceinline__ void cp16(uint32_t dst, const void* src) {
    asm volatile("cp.async.cg.shared.global [%0], [%1], 16;" :: "r"(dst), "l"(src));
}
#define CP_COMMIT() asm volatile("cp.async.commit_group;" ::: "memory")
#define CP_WAIT1()  asm volatile("cp.async.wait_group 1;" ::: "memory")
#define CP_WAIT0()  asm volatile("cp.async.wait_group 0;" ::: "memory")

#define LDSM4(r0, r1, r2, r3, a)                                               \
    asm volatile("ldmatrix.sync.aligned.m8n8.x4.shared.b16 {%0,%1,%2,%3}, [%4];" \
                 : "=r"(r0), "=r"(r1), "=r"(r2), "=r"(r3) : "r"(a))

__device__ __forceinline__ void mma_bf16(float& d0, float& d1, float& d2, float& d3,
                                         uint32_t a0, uint32_t a1, uint32_t a2, uint32_t a3,
                                         uint32_t b0, uint32_t b1) {
    asm volatile(
        "mma.sync.aligned.m16n8k16.row.col.f32.bf16.bf16.f32 "
        "{%0,%1,%2,%3}, {%4,%5,%6,%7}, {%8,%9}, {%0,%1,%2,%3};"
        : "+f"(d0), "+f"(d1), "+f"(d2), "+f"(d3)
        : "r"(a0), "r"(a1), "r"(a2), "r"(a3), "r"(b0), "r"(b1));
}
__device__ __forceinline__ uint32_t pack_bf16(float lo, float hi) {
    uint16_t l = __bfloat16_as_ushort(__float2bfloat16_rn(lo));
    uint16_t h = __bfloat16_as_ushort(__float2bfloat16_rn(hi));
    return (uint32_t)l | ((uint32_t)h << 16);
}

// ================= fp32 -> bf16 split of x =================
__global__ void split_x(const float4* __restrict__ x, uint2* __restrict__ xb,
                        uint2* __restrict__ xs) {
    long i = (long)blockIdx.x * 256 + threadIdx.x;
    float4 v = x[i];
    float bx = __bfloat162float(__float2bfloat16_rn(v.x));
    float by = __bfloat162float(__float2bfloat16_rn(v.y));
    float bz = __bfloat162float(__float2bfloat16_rn(v.z));
    float bw = __bfloat162float(__float2bfloat16_rn(v.w));
    uint2 b, s;
    b.x = pack_bf16(bx, by); b.y = pack_bf16(bz, bw);
    s.x = pack_bf16(v.x - bx, v.y - by);
    s.y = pack_bf16(v.z - bz, v.w - bw);
    xb[i] = b; xs[i] = s;
}

// ================= split-K SIMT SGEMM, B = [k][n] row-major (z slices of 128) =====
__global__ __launch_bounds__(256)
void sgemm_splitk(const float* __restrict__ A, const float* __restrict__ B,
                  float* __restrict__ P, int Arows, int N) {
    __shared__ float As[8][68];
    __shared__ float Bs[8][128];
    const int t = threadIdx.x;
    const int rowBase = blockIdx.y * 64;
    const int colBase = blockIdx.x * 128;
    const int k0 = blockIdx.z * 128;
    const int m0 = (t >> 4) * 4;
    const int n0 = (t & 15) * 8;
    const int am = t >> 2, akq = (t & 3) * 2;
    const int bn = t & 127, bkb = t >> 7;

    float acc[4][8];
#pragma unroll
    for (int i = 0; i < 4; i++)
#pragma unroll
        for (int j = 0; j < 8; j++) acc[i][j] = 0.f;

    for (int kc = 0; kc < 16; kc++) {
        int kk = k0 + kc * 8;
        float2 av = *(const float2*)(A + (long)(rowBase + am) * 1024 + kk + akq);
        As[akq][am] = av.x; As[akq + 1][am] = av.y;
#pragma unroll
        for (int j = 0; j < 4; j++)
            Bs[bkb + 2 * j][bn] = B[(long)(kk + bkb + 2 * j) * N + colBase + bn];
        __syncthreads();
#pragma unroll
        for (int k = 0; k < 8; k++) {
            float a[4], b[8];
            *(float4*)&a[0] = *(const float4*)&As[k][m0];
            *(float4*)&b[0] = *(const float4*)&Bs[k][n0];
            *(float4*)&b[4] = *(const float4*)&Bs[k][n0 + 4];
#pragma unroll
            for (int i = 0; i < 4; i++)
#pragma unroll
                for (int j = 0; j < 8; j++)
                    acc[i][j] = fmaf(a[i], b[j], acc[i][j]);
        }
        __syncthreads();
    }

    float* Pz = P + (long)blockIdx.z * Arows * N;
#pragma unroll
    for (int i = 0; i < 4; i++) {
        float* op = Pz + (long)(rowBase + m0 + i) * N + colBase + n0;
        *(float4*)op       = make_float4(acc[i][0], acc[i][1], acc[i][2], acc[i][3]);
        *(float4*)(op + 4) = make_float4(acc[i][4], acc[i][5], acc[i][6], acc[i][7]);
    }
}

// ================= split-K SIMT SGEMM, B = [n][k] (A@B^T), z slices of 64 =========
__global__ __launch_bounds__(256)
void sgemm_splitk_bt(const float* __restrict__ A, const float* __restrict__ B,
                     float* __restrict__ P, int Arows, int N) {
    __shared__ float As[8][68];
    __shared__ float Bs[8][132];
    const int t = threadIdx.x;
    const int rowBase = blockIdx.y * 64;
    const int colBase = blockIdx.x * 128;
    const int k0 = blockIdx.z * 64;
    const int m0 = (t >> 4) * 4;
    const int n0 = (t & 15) * 8;
    const int am = t >> 2, akq = (t & 3) * 2;
    const int bn = t >> 1, bkq = (t & 1) * 4;

    float acc[4][8];
#pragma unroll
    for (int i = 0; i < 4; i++)
#pragma unroll
        for (int j = 0; j < 8; j++) acc[i][j] = 0.f;

    for (int kc = 0; kc < 8; kc++) {
        int kk = k0 + kc * 8;
        float2 av = *(const float2*)(A + (long)(rowBase + am) * 1024 + kk + akq);
        As[akq][am] = av.x; As[akq + 1][am] = av.y;
        float4 bv = *(const float4*)(B + (long)(colBase + bn) * 1024 + kk + bkq);
        Bs[bkq + 0][bn] = bv.x; Bs[bkq + 1][bn] = bv.y;
        Bs[bkq + 2][bn] = bv.z; Bs[bkq + 3][bn] = bv.w;
        __syncthreads();
#pragma unroll
        for (int k = 0; k < 8; k++) {
            float a[4], b[8];
            *(float4*)&a[0] = *(const float4*)&As[k][m0];
            *(float4*)&b[0] = *(const float4*)&Bs[k][n0];
            *(float4*)&b[4] = *(const float4*)&Bs[k][n0 + 4];
#pragma unroll
            for (int i = 0; i < 4; i++)
#pragma unroll
                for (int j = 0; j < 8; j++)
                    acc[i][j] = fmaf(a[i], b[j], acc[i][j]);
        }
        __syncthreads();
    }

    float* Pz = P + (long)blockIdx.z * Arows * N;
#pragma unroll
    for (int i = 0; i < 4; i++) {
        float* op = Pz + (long)(rowBase + m0 + i) * N + colBase + n0;
        *(float4*)op       = make_float4(acc[i][0], acc[i][1], acc[i][2], acc[i][3]);
        *(float4*)(op + 4) = make_float4(acc[i][4], acc[i][5], acc[i][6], acc[i][7]);
    }
}

// ================= split-K reduce + bias (nz partials) =================
__global__ void reduce_splitk(const float* __restrict__ P, const float* __restrict__ bias,
                              float* __restrict__ C, int total, int N, int nz) {
    int i = blockIdx.x * 256 + threadIdx.x;
    if (i < total) {
        float s = 0.f;
        for (int z = 0; z < nz; z++) s += P[(long)z * total + i];
        C[i] = s + bias[i % N];
    }
}

// ================= build M^T (bf16 split) + c, tiled, fused k-reduce =================
#define BM_SMEM ((8192 + 4096 + 64) * 4)
__global__ __launch_bounds__(256)
void build_M_c(const float* __restrict__ ipw, const float* __restrict__ ipb,
               const float* __restrict__ part,
               bf16* __restrict__ MTb, bf16* __restrict__ MTs, float* __restrict__ c) {
    extern __shared__ float bm[];
    float* wqs = bm;             // [64][128]
    float* ksm = bm + 8192;      // [64][64]  (e, hd)
    float* bqs = ksm + 4096;     // [64]
    const int h = blockIdx.y;
    const int d0 = blockIdx.x * 128;
    const int t = threadIdx.x;

    for (int idx = t; idx < 8192; idx += 256) {
        int hd = idx >> 7, dd = idx & 127;
        wqs[idx] = ipw[(long)(h * 64 + hd) * 1024 + d0 + dd];
    }
    for (int idx = t; idx < 4096; idx += 256) {
        int e = idx >> 6, hd = idx & 63;
        float s = 0.f;
#pragma unroll
        for (int z = 0; z < 16; z++)
            s += part[(long)z * 131072 + e * 2048 + h * 64 + hd];
        ksm[idx] = s + ipb[1024 + h * 64 + hd];
    }
    if (t < 64) bqs[t] = ipb[h * 64 + t];
    __syncthreads();

    const int dd = t & 127;
    const int e0 = (t >> 7) * 32;
#pragma unroll
    for (int eb = 0; eb < 4; eb++) {
        float acc[8];
#pragma unroll
        for (int i = 0; i < 8; i++) acc[i] = 0.f;
#pragma unroll 8
        for (int hd = 0; hd < 64; hd++) {
            float wv = wqs[hd * 128 + dd];
#pragma unroll
            for (int e8 = 0; e8 < 8; e8++)
                acc[e8] = fmaf(wv, ksm[(e0 + eb * 8 + e8) * 64 + hd], acc[e8]);
        }
#pragma unroll
        for (int e8 = 0; e8 < 8; e8++) {
            int he = h * 64 + e0 + eb * 8 + e8;
            bf16 b = __float2bfloat16_rn(acc[e8]);
            MTb[(long)he * 1024 + d0 + dd] = b;
            MTs[(long)he * 1024 + d0 + dd] =
                __float2bfloat16_rn(acc[e8] - __bfloat162float(b));
        }
    }
    if (blockIdx.x == 0 && t < 64) {
        float s = 0.f;
        for (int hd = 0; hd < 64; hd++) s = fmaf(ksm[t * 64 + hd], bqs[hd], s);
        c[h * 64 + t] = s;
    }
}

// ================= build Gt (bf16 split) + c2 =================
__global__ void build_Gt(const float* __restrict__ W2gT, const float* __restrict__ kv,
                         const float* __restrict__ gw1, const float* __restrict__ opb,
                         const float* __restrict__ gb1,
                         bf16* __restrict__ Gtb, bf16* __restrict__ Gts,
                         float* __restrict__ c2) {
    int j = blockIdx.x;
    __shared__ float wrow[1024];
    int t = threadIdx.x;
    for (int i = t; i < 1024; i += 256) wrow[i] = W2gT[(long)j * 1024 + i];
    __syncthreads();
    for (int he = t; he < 1024; he += 256) {
        int h = he >> 6, e = he & 63;
        const float* v = kv + (long)e * 2048 + 1024 + h * 64;
        float s = 0.f;
#pragma unroll 8
        for (int hd = 0; hd < 64; hd++)
            s = fmaf(v[hd], wrow[h * 64 + hd], s);
        bf16 b = __float2bfloat16_rn(s);
        Gtb[(long)j * 1024 + he] = b;
        Gts[(long)j * 1024 + he] = __float2bfloat16_rn(s - __bfloat162float(b));
    }
    if (t < 32) {
        float s = 0.f;
        const float* g = gw1 + (long)j * 1024;
        for (int d = t; d < 1024; d += 32) s = fmaf(opb[d], g[d], s);
#pragma unroll
        for (int off = 16; off > 0; off >>= 1)
            s += __shfl_xor_sync(0xffffffffu, s, off);
        if (t == 0) c2[j] = s + gb1[j];
    }
}

// ================= bf16 3-split tensor-core GEMM (ldmatrix + mma.sync) =================
// MODE 1: softmax epilogue; signals flags[blockIdx.y] when its attn tile is stored.
// MODE 2: GELU epilogue; prefetches B (Gt, ready early), then spins on flags[y]
//         (attn row-block ready) before loading A. Launched on a low-priority
//         stream so its CTAs only fill SM slots GEMM1 no longer needs.
#define ROWW 20
#define TILE_B 10240
#define STAGE_B (4 * TILE_B)
#define SMEM_BYTES (2 * STAGE_B)

template<int MODE>
__global__ __launch_bounds__(256, 2)
void tgemm(const bf16* __restrict__ Ab, const bf16* __restrict__ As,
           const bf16* __restrict__ Bb, const bf16* __restrict__ Bs,
           const float* __restrict__ bias,
           uint32_t* __restrict__ outB, uint32_t* __restrict__ outS,
           float* __restrict__ outF, int Ncols, int* flags) {
    extern __shared__ uint32_t sm32[];
    uint32_t smu = smem_u32(sm32);

    const int t = threadIdx.x;
    const int w = t >> 5, lane = t & 31;
    const int wm = w >> 1, wn = w & 1;
    const int q = lane >> 2, c4 = lane & 3;

    const int rowBase = blockIdx.y * 128;
    const int colBase = blockIdx.x * 128;

    const int lr = t >> 1;
    const int ls = t & 1;
    const bf16* gAb = Ab + (long)(rowBase + lr) * 1024;
    const bf16* gAs = As + (long)(rowBase + lr) * 1024;
    const bf16* gBb = Bb + (long)(colBase + lr) * 1024;
    const bf16* gBs = Bs + (long)(colBase + lr) * 1024;
    const uint32_t dRow = smu + lr * (ROWW * 4);

    const int lm8 = lane & 7;
    const uint32_t aOff = (uint32_t)(wm * 32 + lm8 + ((lane >> 3) & 1) * 8) * 80
                          + ((lane >> 4) & 1) * 16;
    const uint32_t bOff = (uint32_t)(wn * 64 + lm8 + ((lane >> 4) & 1) * 8) * 80
                          + ((lane >> 3) & 1) * 16;

    float acc[2][8][4];
#pragma unroll
    for (int mt = 0; mt < 2; mt++)
#pragma unroll
        for (int nt = 0; nt < 8; nt++)
#pragma unroll
            for (int i = 0; i < 4; i++) acc[mt][nt][i] = 0.f;

#define LOAD_STAGE_A(st, ck) do {                                                \
    int kofs = (ck) * 32;                                                        \
    uint32_t sb = (st) * STAGE_B;                                                \
    _Pragma("unroll")                                                            \
    for (int j = 0; j < 2; j++) {                                                \
        int seg = ls * 2 + j;                                                    \
        cp16(dRow + sb + 0 * TILE_B + seg * 16, gAb + kofs + seg * 8);           \
        cp16(dRow + sb + 1 * TILE_B + seg * 16, gAs + kofs + seg * 8);           \
    }                                                                            \
} while (0)
#define LOAD_STAGE_BT(st, ck) do {                                               \
    int kofs = (ck) * 32;                                                        \
    uint32_t sb = (st) * STAGE_B;                                                \
    _Pragma("unroll")                                                            \
    for (int j = 0; j < 2; j++) {                                                \
        int seg = ls * 2 + j;                                                    \
        cp16(dRow + sb + 2 * TILE_B + seg * 16, gBb + kofs + seg * 8);           \
        cp16(dRow + sb + 3 * TILE_B + seg * 16, gBs + kofs + seg * 8);           \
    }                                                                            \
} while (0)

    if (MODE == 2) {
        // B (Gt) is ready before attn: prefetch it, then wait for this
        // row-block's attn tiles (8 producer CTAs) to be published.
        LOAD_STAGE_BT(0, 0);
        CP_COMMIT();
        if (t == 0) {
            while (atomicAdd(flags + blockIdx.y, 0) < 8) __nanosleep(128);
        }
        __syncthreads();
        __threadfence();
        LOAD_STAGE_A(0, 0);
        CP_COMMIT();
    } else {
        LOAD_STAGE_A(0, 0);
        LOAD_STAGE_BT(0, 0);
        CP_COMMIT();
    }

    const int NC = 1024 / 32;
    for (int ck = 0; ck < NC; ck++) {
        int buf = ck & 1;
        if (ck + 1 < NC) {
            LOAD_STAGE_A(buf ^ 1, ck + 1);
            LOAD_STAGE_BT(buf ^ 1, ck + 1);
            CP_COMMIT();
            CP_WAIT1();
        } else {
            CP_WAIT0();
        }
        __syncthreads();

        const uint32_t s0 = smu + buf * STAGE_B;
        const uint32_t aAb = s0 + aOff;
        const uint32_t aAs = s0 + TILE_B + aOff;
        const uint32_t bBb = s0 + 2 * TILE_B + bOff;
        const uint32_t bBs = s0 + 3 * TILE_B + bOff;

#pragma unroll
        for (int ks = 0; ks < 2; ks++) {
            uint32_t fab[2][4], fas[2][4];
            LDSM4(fab[0][0], fab[0][1], fab[0][2], fab[0][3], aAb + ks * 32);
            LDSM4(fab[1][0], fab[1][1], fab[1][2], fab[1][3], aAb + 1280 + ks * 32);
            LDSM4(fas[0][0], fas[0][1], fas[0][2], fas[0][3], aAs + ks * 32);
            LDSM4(fas[1][0], fas[1][1], fas[1][2], fas[1][3], aAs + 1280 + ks * 32);
#pragma unroll
            for (int jh = 0; jh < 2; jh++) {
                uint32_t fbb[4][2], fbs[4][2];
                LDSM4(fbb[0][0], fbb[0][1], fbb[1][0], fbb[1][1],
                      bBb + (2 * jh) * 1280 + ks * 32);
                LDSM4(fbb[2][0], fbb[2][1], fbb[3][0], fbb[3][1],
                      bBb + (2 * jh + 1) * 1280 + ks * 32);
                LDSM4(fbs[0][0], fbs[0][1], fbs[1][0], fbs[1][1],
                      bBs + (2 * jh) * 1280 + ks * 32);
                LDSM4(fbs[2][0], fbs[2][1], fbs[3][0], fbs[3][1],
                      bBs + (2 * jh + 1) * 1280 + ks * 32);
#pragma unroll
                for (int l = 0; l < 4; l++)
#pragma unroll
                    for (int mt = 0; mt < 2; mt++) {
                        float* d = acc[mt][4 * jh + l];
                        mma_bf16(d[0], d[1], d[2], d[3],
                                 fab[mt][0], fab[mt][1], fab[mt][2], fab[mt][3],
                                 fbb[l][0], fbb[l][1]);
                    }
#pragma unroll
                for (int l = 0; l < 4; l++)
#pragma unroll
                    for (int mt = 0; mt < 2; mt++) {
                        float* d = acc[mt][4 * jh + l];
                        mma_bf16(d[0], d[1], d[2], d[3],
                                 fab[mt][0], fab[mt][1], fab[mt][2], fab[mt][3],
                                 fbs[l][0], fbs[l][1]);
                    }
#pragma unroll
                for (int l = 0; l < 4; l++)
#pragma unroll
                    for (int mt = 0; mt < 2; mt++) {
                        float* d = acc[mt][4 * jh + l];
                        mma_bf16(d[0], d[1], d[2], d[3],
                                 fas[mt][0], fas[mt][1], fas[mt][2], fas[mt][3],
                                 fbb[l][0], fbb[l][1]);
                    }
            }
        }
        __syncthreads();
    }

    const int colB = colBase + wn * 64;
    float bv[16];
#pragma unroll
    for (int nt = 0; nt < 8; nt++) {
#pragma unroll
        for (int j = 0; j < 2; j++)
            bv[nt * 2 + j] = bias[colB + nt * 8 + 2 * c4 + j];
    }

#pragma unroll
    for (int mt = 0; mt < 2; mt++) {
#pragma unroll
        for (int h = 0; h < 2; h++) {
            int row = rowBase + wm * 32 + mt * 16 + q + h * 8;
            float v[16];
#pragma unroll
            for (int nt = 0; nt < 8; nt++) {
                v[nt * 2 + 0] = acc[mt][nt][2 * h + 0] + bv[nt * 2 + 0];
                v[nt * 2 + 1] = acc[mt][nt][2 * h + 1] + bv[nt * 2 + 1];
            }
            if (MODE == 1) {
#pragma unroll
                for (int i = 0; i < 16; i++) v[i] *= 0.125f;
                float m = v[0];
#pragma unroll
                for (int i = 1; i < 16; i++) m = fmaxf(m, v[i]);
                m = fmaxf(m, __shfl_xor_sync(0xffffffffu, m, 1));
                m = fmaxf(m, __shfl_xor_sync(0xffffffffu, m, 2));
                float s = 0.f;
#pragma unroll
                for (int i = 0; i < 16; i++) { v[i] = __expf(v[i] - m); s += v[i]; }
                s += __shfl_xor_sync(0xffffffffu, s, 1);
                s += __shfl_xor_sync(0xffffffffu, s, 2);
                float inv = 1.f / s;
#pragma unroll
                for (int i = 0; i < 16; i++) v[i] *= inv;
                uint32_t* ob = outB + (long)row * (Ncols / 2) + (colB >> 1) + c4;
                uint32_t* os = outS + (long)row * (Ncols / 2) + (colB >> 1) + c4;
#pragma unroll
                for (int nt = 0; nt < 8; nt++) {
                    float v0 = v[nt * 2], v1 = v[nt * 2 + 1];
                    float b0 = __bfloat162float(__float2bfloat16_rn(v0));
                    float b1 = __bfloat162float(__float2bfloat16_rn(v1));
                    ob[nt * 4] = pack_bf16(b0, b1);
                    os[nt * 4] = pack_bf16(v0 - b0, v1 - b1);
                }
            }
            if (MODE == 2) {
#pragma unroll
                for (int i = 0; i < 16; i++)
                    v[i] = 0.5f * v[i] * (1.0f + erff(v[i] * 0.70710678118654752f));
                float* op = outF + (long)row * Ncols + colB + 2 * c4;
#pragma unroll
                for (int nt = 0; nt < 8; nt++) {
                    op[nt * 8 + 0] = v[nt * 2 + 0];
                    op[nt * 8 + 1] = v[nt * 2 + 1];
                }
            }
        }
    }

    if (MODE == 1) {
        // publish this attn tile: all stores above, then count arrival
        __threadfence();
        __syncthreads();
        if (t == 0) atomicAdd(flags + blockIdx.y, 1);
    }
#undef LOAD_STAGE_A
#undef LOAD_STAGE_BT
}

// ================= gating: smem-cached w2, 16 tokens/block =================
#define GATE_SMEM (64 * 257 * 4 + 4 * 256 * 4 + 4 * 64 * 4)

__global__ __launch_bounds__(256)
void gating_kernel(const float* __restrict__ h1, const float* __restrict__ w2,
                   const float* __restrict__ b2, float* __restrict__ out) {
    extern __shared__ float gs[];
    float* w2s  = gs;
    float* hrow = gs + 64 * 257;
    float* lg   = hrow + 4 * 256;
    int t = threadIdx.x;
    int grp = t >> 6, e = t & 63;
    for (int i = t; i < 64 * 256; i += 256)
        w2s[(i >> 8) * 257 + (i & 255)] = w2[i];
    __syncthreads();

    for (int rep = 0; rep < 4; rep++) {
        int token = blockIdx.x * 16 + rep * 4 + grp;
        for (int j = e; j < 256; j += 64) hrow[grp * 256 + j] = h1[(long)token * 256 + j];
        __syncthreads();
        float acc = 0.f;
        const float* wr = w2s + e * 257;
        const float* hr = hrow + grp * 256;
#pragma unroll 8
        for (int j = 0; j < 256; j++) acc = fmaf(hr[j], wr[j], acc);
        lg[grp * 64 + e] = acc + b2[e];
        __syncthreads();
        if (e == 0) {
            const float* L = lg + grp * 64;
            int i1 = 0; float v1 = L[0];
            for (int k = 1; k < NEXP; k++) if (L[k] > v1) { v1 = L[k]; i1 = k; }
            int i2 = -1; float v2 = -1e30f;
            for (int k = 0; k < NEXP; k++) if (k != i1 && L[k] > v2) { v2 = L[k]; i2 = k; }
            float s = 0.f;
            for (int k = 0; k < NEXP; k++) s += __expf(L[k] - v1);
            float p1 = 1.0f / s;
            float p2 = __expf(v2 - v1) / s;
            float wsum = p1 + p2 + 1e-8f;
            out[token * 2 + 0] = (float)i1;
            out[token * 2 + 1] = (float)i2;
            out[NTOK * 2 + token * 2 + 0] = p1 / wsum;
            out[NTOK * 2 + token * 2 + 1] = p2 / wsum;
        }
        __syncthreads();
    }
}

// ================= launch =================
extern "C" void kernel_launch(void* const* d_in, const int* in_sizes, int n_in,
                              void* d_out, int out_size) {
    const float* x   = (const float*)d_in[0];
    const float* emb = (const float*)d_in[1];
    const float* ipw = (const float*)d_in[2];
    const float* ipb = (const float*)d_in[3];
    const float* opw = (const float*)d_in[4];
    const float* opb = (const float*)d_in[5];
    const float* gw1 = (const float*)d_in[6];
    const float* gb1 = (const float*)d_in[7];
    const float* gw2 = (const float*)d_in[8];
    const float* gb2 = (const float*)d_in[9];
    float* out = (float*)d_out;

    float *kv, *c, *W2gT, *c2, *part, *part2, *h1, *zero;
    int* flags;
    bf16 *MTb, *MTs, *Gtb, *Gts, *xb, *xs, *ab, *as_;
    cudaGetSymbolAddress((void**)&kv,    g_kv);
    cudaGetSymbolAddress((void**)&c,     g_c);
    cudaGetSymbolAddress((void**)&W2gT,  g_W2gT);
    cudaGetSymbolAddress((void**)&c2,    g_c2);
    cudaGetSymbolAddress((void**)&part,  g_part);
    cudaGetSymbolAddress((void**)&part2, g_part2);
    cudaGetSymbolAddress((void**)&flags, g_flags);
    cudaGetSymbolAddress((void**)&h1,    g_h1);
    cudaGetSymbolAddress((void**)&zero,  g_zero);
    cudaGetSymbolAddress((void**)&MTb,   g_MTb);
    cudaGetSymbolAddress((void**)&MTs,   g_MTs);
    cudaGetSymbolAddress((void**)&Gtb,   g_Gtb);
    cudaGetSymbolAddress((void**)&Gts,   g_Gts);
    cudaGetSymbolAddress((void**)&xb,    g_xb);
    cudaGetSymbolAddress((void**)&xs,    g_xs);
    cudaGetSymbolAddress((void**)&ab,    g_ab);
    cudaGetSymbolAddress((void**)&as_,   g_as);

    static cudaStream_t s1 = nullptr, s2 = nullptr, s3 = nullptr;
    static cudaEvent_t evRoot = nullptr, evSplit = nullptr, evKv = nullptr,
                       evGt = nullptr, evDone = nullptr;
    if (s1 == nullptr) {
        int loPri = 0, hiPri = 0;
        cudaDeviceGetStreamPriorityRange(&loPri, &hiPri);   // loPri = least urgent
        cudaStreamCreateWithFlags(&s1, cudaStreamNonBlocking);
        cudaStreamCreateWithFlags(&s2, cudaStreamNonBlocking);
        cudaStreamCreateWithPriority(&s3, cudaStreamNonBlocking, loPri);
        cudaEventCreateWithFlags(&evRoot,  cudaEventDisableTiming);
        cudaEventCreateWithFlags(&evSplit, cudaEventDisableTiming);
        cudaEventCreateWithFlags(&evKv,    cudaEventDisableTiming);
        cudaEventCreateWithFlags(&evGt,    cudaEventDisableTiming);
        cudaEventCreateWithFlags(&evDone,  cudaEventDisableTiming);
        cudaFuncSetAttribute(tgemm<1>, cudaFuncAttributeMaxDynamicSharedMemorySize, SMEM_BYTES);
        cudaFuncSetAttribute(tgemm<2>, cudaFuncAttributeMaxDynamicSharedMemorySize, SMEM_BYTES);
        cudaFuncSetAttribute(gating_kernel, cudaFuncAttributeMaxDynamicSharedMemorySize, GATE_SMEM);
        cudaFuncSetAttribute(build_M_c, cudaFuncAttributeMaxDynamicSharedMemorySize, BM_SMEM);
    }

    // reset producer/consumer flags (must precede GEMM1 and GEMM2')
    cudaMemsetAsync(flags, 0, 128 * sizeof(int), 0);

    // fork
    cudaEventRecord(evRoot, 0);
    cudaStreamWaitEvent(s1, evRoot, 0);
    cudaStreamWaitEvent(s2, evRoot, 0);

    // s1: split x (input to GEMM1)
    split_x<<<NTOK * DMODEL / 4 / 256, 256, 0, s1>>>((const float4*)x, (uint2*)xb, (uint2*)xs);
    cudaEventRecord(evSplit, s1);

    // s2: W2gT chain (independent of kv until build_Gt)
    sgemm_splitk<<<dim3(8, 4, 8), 256, 0, s2>>>(gw1, opw, part2, 256, 1024);
    reduce_splitk<<<(256 * 1024 + 255) / 256, 256, 0, s2>>>(part2, zero, W2gT, 256 * 1024, 1024, 8);

    // s0: kv partials (critical path), split-K=16
    sgemm_splitk_bt<<<dim3(16, 1, 16), 256>>>(emb, ipw + 1024 * 1024, part, 64, 2048);
    cudaEventRecord(evKv, 0);

    // s2: kv reduce (v half) + build_Gt, hidden under build_M_c/GEMM1
    cudaStreamWaitEvent(s2, evKv, 0);
    reduce_splitk<<<(64 * 2048 + 255) / 256, 256, 0, s2>>>(part, ipb + 1024, kv, 64 * 2048, 2048, 16);
    build_Gt<<<256, 256, 0, s2>>>(W2gT, kv, gw1, opb, gb1, Gtb, Gts, c2);
    cudaEventRecord(evGt, s2);

    // s0: M builder then GEMM1 (single launch; signals flags per row-block)
    build_M_c<<<dim3(8, 16), 256, BM_SMEM>>>(ipw, ipb, part, MTb, MTs, c);
    cudaStreamWaitEvent(0, evSplit, 0);
    tgemm<1><<<dim3(8, 128), 256, SMEM_BYTES>>>(xb, xs, MTb, MTs, c,
                                                (uint32_t*)ab, (uint32_t*)as_, nullptr,
                                                1024, flags);

    // s3 (low priority): GEMM2' overlapping GEMM1's tail via flags, then gating
    cudaStreamWaitEvent(s3, evGt, 0);
    tgemm<2><<<dim3(2, 128), 256, SMEM_BYTES, s3>>>(ab, as_, Gtb, Gts, c2,
                                                    nullptr, nullptr, h1, 256, flags);
    gating_kernel<<<NTOK / 16, 256, GATE_SMEM, s3>>>(h1, gw2, gb2, out);
    cudaEventRecord(evDone, s3);

    // join s3 back into the capture origin stream
    cudaStreamWaitEvent(0, evDone, 0);
    (void)in_sizes; (void)n_in; (void)out_size;
}